// round 1
// baseline (speedup 1.0000x reference)
#include <cuda_runtime.h>
#include <math.h>

#define BATCH 4
#define HH 256
#define WW 256
#define HW 65536
#define C1 64
#define C2 128
#define NPAT 30
#define NANOM 32
#define QCIN 190

// d_out element offsets (outputs concatenated in reference return order)
#define FEAT_OFF 0UL
#define RL_OFF   33554432UL
#define AL_OFF   34340864UL
#define AM_OFF   34603008UL
#define ANM_OFF  42467328UL
#define QS_OFF   50855936UL
#define RP_OFF   51118080UL
#define AP_OFF   51904512UL

// scratch (device globals; no allocations allowed)
__device__ float g_h1[BATCH * C1 * HW];     // conv1 out (pre-bn)
__device__ float g_feat[BATCH * C2 * HW];   // conv2 out (pre-bn)
__device__ float g_stats1[2 * C1];          // [a | s] affine for bn1
__device__ float g_stats2[2 * C2];          // [a | s] affine for bn2
__device__ float g_mw[64 * C2 * 9];         // packed matcher weights (62 real + 2 zero)

__device__ __forceinline__ float sigmoidf_(float v) {
    return 1.f / (1.f + __expf(-v));
}

// ---------------------------------------------------------------------------
// conv1: 3 -> 64, 3x3 pad 1, bias. Tile 32x16, thread = 2 px x 16 oc.
// grid (8, 16, BATCH*4), block 256
// ---------------------------------------------------------------------------
__global__ void conv1_kernel(const float* __restrict__ x,
                             const float* __restrict__ w,
                             const float* __restrict__ bias) {
    __shared__ float s_in[3][18][34];
    __shared__ float s_w[27 * 16];
    int tid = threadIdx.x;
    int bx = blockIdx.x, by = blockIdx.y;
    int b = blockIdx.z >> 2, g = blockIdx.z & 3;

    for (int i = tid; i < 3 * 18 * 34; i += 256) {
        int ci = i / 612;
        int r = (i % 612) / 34;
        int c = i % 34;
        int y = by * 16 - 1 + r, xx = bx * 32 - 1 + c;
        float v = 0.f;
        if (y >= 0 && y < HH && xx >= 0 && xx < WW)
            v = x[((size_t)(b * 3 + ci)) * HW + (size_t)y * WW + xx];
        s_in[ci][r][c] = v;
    }
    for (int i = tid; i < 27 * 16; i += 256) {
        int o = i & 15, rest = i >> 4;            // rest = ci*9+k
        s_w[i] = w[(g * 16 + o) * 27 + rest];
    }
    __syncthreads();

    int tx = tid & 15, ty = tid >> 4;
    float acc0[16], acc1[16];
#pragma unroll
    for (int o = 0; o < 16; ++o) {
        float bb = bias[g * 16 + o];
        acc0[o] = bb; acc1[o] = bb;
    }
#pragma unroll
    for (int ci = 0; ci < 3; ++ci)
#pragma unroll
        for (int k = 0; k < 9; ++k) {
            int ky = k / 3, kx = k % 3;
            float v0 = s_in[ci][ty + ky][tx + kx];
            float v1 = s_in[ci][ty + ky][tx + 16 + kx];
            const float* wp = &s_w[(ci * 9 + k) * 16];
#pragma unroll
            for (int o = 0; o < 16; ++o) {
                float ww = wp[o];
                acc0[o] = fmaf(v0, ww, acc0[o]);
                acc1[o] = fmaf(v1, ww, acc1[o]);
            }
        }
    int gy = by * 16 + ty, gx = bx * 32 + tx;
#pragma unroll
    for (int o = 0; o < 16; ++o) {
        size_t base = ((size_t)(b * C1 + g * 16 + o)) * HW + (size_t)gy * WW;
        g_h1[base + gx] = acc0[o];
        g_h1[base + gx + 16] = acc1[o];
    }
}

// ---------------------------------------------------------------------------
// batchnorm stats -> affine (a = gamma/sqrt(var+eps), s = beta - mean*a)
// One block per channel; deterministic tree reduction, double accumulators.
// which: 0 = g_h1/C1, 1 = g_feat/C2
// ---------------------------------------------------------------------------
__global__ void stats_kernel(int which,
                             const float* __restrict__ gamma,
                             const float* __restrict__ beta) {
    __shared__ double s_sum[256];
    __shared__ double s_sq[256];
    int c = blockIdx.x, tid = threadIdx.x;
    const float* src = which ? g_feat : g_h1;
    float* stats = which ? g_stats2 : g_stats1;
    int C = which ? C2 : C1;

    double sum = 0.0, sq = 0.0;
    for (int b = 0; b < BATCH; ++b) {
        const float* p = src + ((size_t)(b * C + c)) * HW;
        for (int i = tid; i < HW; i += 256) {
            double v = (double)p[i];
            sum += v;
            sq += v * v;
        }
    }
    s_sum[tid] = sum; s_sq[tid] = sq;
    __syncthreads();
    for (int s = 128; s > 0; s >>= 1) {
        if (tid < s) { s_sum[tid] += s_sum[tid + s]; s_sq[tid] += s_sq[tid + s]; }
        __syncthreads();
    }
    if (tid == 0) {
        double n = (double)BATCH * (double)HW;
        double mean = s_sum[0] / n;
        double var = s_sq[0] / n - mean * mean;
        double a = (double)gamma[c] / sqrt(var + 1e-5);
        stats[c] = (float)a;
        stats[C + c] = (float)((double)beta[c] - mean * a);
    }
}

// ---------------------------------------------------------------------------
// conv2: 64 -> 128, 3x3 pad 1, bias; bn1+relu fused into tile load.
// Tile 32x32, thread = 4 px x 16 oc, ci chunks of 8.
// grid (8, 8, BATCH*8), block 256
// ---------------------------------------------------------------------------
__global__ void conv2_kernel(const float* __restrict__ w2,
                             const float* __restrict__ bias) {
    __shared__ float s_in[8][34][34];
    __shared__ float s_w[72 * 16];   // [ci*9+k][o]
    int tid = threadIdx.x;
    int bx = blockIdx.x, by = blockIdx.y;
    int b = blockIdx.z >> 3, g = blockIdx.z & 7;
    int tx = tid & 15, ty = tid >> 4;
    int x0 = bx * 32, y0 = by * 32;

    float acc[4][16];
#pragma unroll
    for (int o = 0; o < 16; ++o) {
        float bb = bias[g * 16 + o];
        acc[0][o] = bb; acc[1][o] = bb; acc[2][o] = bb; acc[3][o] = bb;
    }

    for (int cb = 0; cb < C1; cb += 8) {
        __syncthreads();
        for (int i = tid; i < 8 * 34 * 34; i += 256) {
            int ci = i / 1156;
            int r = (i % 1156) / 34;
            int c = i % 34;
            int y = y0 - 1 + r, xx = x0 - 1 + c;
            float v = 0.f;
            if (y >= 0 && y < HH && xx >= 0 && xx < WW) {
                int ch = cb + ci;
                float raw = g_h1[((size_t)(b * C1 + ch)) * HW + (size_t)y * WW + xx];
                v = fmaxf(fmaf(g_stats1[ch], raw, g_stats1[C1 + ch]), 0.f);
            }
            s_in[ci][r][c] = v;
        }
        for (int i = tid; i < 72 * 16; i += 256) {
            int o = i & 15, rest = i >> 4;        // rest = ci*9+k
            int ci = rest / 9, k = rest % 9;
            s_w[i] = w2[(g * 16 + o) * (C1 * 9) + (cb + ci) * 9 + k];
        }
        __syncthreads();

#pragma unroll
        for (int ci = 0; ci < 8; ++ci)
#pragma unroll
            for (int k = 0; k < 9; ++k) {
                int ky = k / 3, kx = k % 3;
                float v00 = s_in[ci][ty + ky][tx + kx];
                float v01 = s_in[ci][ty + ky][tx + 16 + kx];
                float v10 = s_in[ci][ty + 16 + ky][tx + kx];
                float v11 = s_in[ci][ty + 16 + ky][tx + 16 + kx];
                const float* wp = &s_w[(ci * 9 + k) * 16];
#pragma unroll
                for (int o = 0; o < 16; ++o) {
                    float ww = wp[o];
                    acc[0][o] = fmaf(v00, ww, acc[0][o]);
                    acc[1][o] = fmaf(v01, ww, acc[1][o]);
                    acc[2][o] = fmaf(v10, ww, acc[2][o]);
                    acc[3][o] = fmaf(v11, ww, acc[3][o]);
                }
            }
    }
#pragma unroll
    for (int o = 0; o < 16; ++o) {
        size_t base = ((size_t)(b * C2 + g * 16 + o)) * HW;
        g_feat[base + (size_t)(y0 + ty) * WW + x0 + tx]            = acc[0][o];
        g_feat[base + (size_t)(y0 + ty) * WW + x0 + tx + 16]       = acc[1][o];
        g_feat[base + (size_t)(y0 + ty + 16) * WW + x0 + tx]       = acc[2][o];
        g_feat[base + (size_t)(y0 + ty + 16) * WW + x0 + tx + 16]  = acc[3][o];
    }
}

// ---------------------------------------------------------------------------
// bn2 + relu, g_feat -> d_out features slab (vectorized float4)
// ---------------------------------------------------------------------------
__global__ void bn2_kernel(float4* __restrict__ out) {
    int i = blockIdx.x * 256 + threadIdx.x;          // over n/4 = 8388608
    int c = (i >> 14) & 127;                          // (i*4 >> 16) & 127
    float a = g_stats2[c], s = g_stats2[C2 + c];
    float4 v = ((const float4*)g_feat)[i];
    v.x = fmaxf(fmaf(a, v.x, s), 0.f);
    v.y = fmaxf(fmaf(a, v.y, s), 0.f);
    v.z = fmaxf(fmaf(a, v.z, s), 0.f);
    v.w = fmaxf(fmaf(a, v.w, s), 0.f);
    out[i] = v;
}

// ---------------------------------------------------------------------------
// pack matcher weights: [core(10) | clad(10) | ferr(10) | anom(32) | zero(2)]
// ---------------------------------------------------------------------------
__global__ void pack_mw_kernel(const float* __restrict__ core,
                               const float* __restrict__ clad,
                               const float* __restrict__ ferr,
                               const float* __restrict__ anom) {
    int i = blockIdx.x * 256 + threadIdx.x;
    if (i >= 64 * C2 * 9) return;
    int oc = i / (C2 * 9), rem = i % (C2 * 9);
    float v = 0.f;
    if (oc < 10)      v = core[oc * (C2 * 9) + rem];
    else if (oc < 20) v = clad[(oc - 10) * (C2 * 9) + rem];
    else if (oc < 30) v = ferr[(oc - 20) * (C2 * 9) + rem];
    else if (oc < 62) v = anom[(oc - 30) * (C2 * 9) + rem];
    g_mw[i] = v;
}

// ---------------------------------------------------------------------------
// matcher conv: 128 -> 62 (padded 64), 3x3 pad 1, no bias, sigmoid.
// Reads final features from d_out; writes all_matches/anomaly_matches slabs.
// grid (8, 8, BATCH*4), block 256
// ---------------------------------------------------------------------------
__global__ void matcher_kernel(const float* __restrict__ feat,
                               float* __restrict__ out) {
    __shared__ float s_in[8][34][34];
    __shared__ float s_w[72 * 16];
    int tid = threadIdx.x;
    int bx = blockIdx.x, by = blockIdx.y;
    int b = blockIdx.z >> 2, g = blockIdx.z & 3;
    int tx = tid & 15, ty = tid >> 4;
    int x0 = bx * 32, y0 = by * 32;

    float acc[4][16];
#pragma unroll
    for (int o = 0; o < 16; ++o) {
        acc[0][o] = 0.f; acc[1][o] = 0.f; acc[2][o] = 0.f; acc[3][o] = 0.f;
    }

    for (int cb = 0; cb < C2; cb += 8) {
        __syncthreads();
        for (int i = tid; i < 8 * 34 * 34; i += 256) {
            int ci = i / 1156;
            int r = (i % 1156) / 34;
            int c = i % 34;
            int y = y0 - 1 + r, xx = x0 - 1 + c;
            float v = 0.f;
            if (y >= 0 && y < HH && xx >= 0 && xx < WW)
                v = feat[((size_t)(b * C2 + cb + ci)) * HW + (size_t)y * WW + xx];
            s_in[ci][r][c] = v;
        }
        for (int i = tid; i < 72 * 16; i += 256) {
            int o = i & 15, rest = i >> 4;
            int ci = rest / 9, k = rest % 9;
            s_w[i] = g_mw[(g * 16 + o) * (C2 * 9) + (cb + ci) * 9 + k];
        }
        __syncthreads();

#pragma unroll
        for (int ci = 0; ci < 8; ++ci)
#pragma unroll
            for (int k = 0; k < 9; ++k) {
                int ky = k / 3, kx = k % 3;
                float v00 = s_in[ci][ty + ky][tx + kx];
                float v01 = s_in[ci][ty + ky][tx + 16 + kx];
                float v10 = s_in[ci][ty + 16 + ky][tx + kx];
                float v11 = s_in[ci][ty + 16 + ky][tx + 16 + kx];
                const float* wp = &s_w[(ci * 9 + k) * 16];
#pragma unroll
                for (int o = 0; o < 16; ++o) {
                    float ww = wp[o];
                    acc[0][o] = fmaf(v00, ww, acc[0][o]);
                    acc[1][o] = fmaf(v01, ww, acc[1][o]);
                    acc[2][o] = fmaf(v10, ww, acc[2][o]);
                    acc[3][o] = fmaf(v11, ww, acc[3][o]);
                }
            }
    }
#pragma unroll
    for (int o = 0; o < 16; ++o) {
        int oc = g * 16 + o;
        if (oc >= 62) continue;
        size_t base;
        if (oc < NPAT) base = AM_OFF + ((size_t)(b * NPAT + oc)) * HW;
        else           base = ANM_OFF + ((size_t)(b * NANOM + (oc - NPAT))) * HW;
        out[base + (size_t)(y0 + ty) * WW + x0 + tx]           = sigmoidf_(acc[0][o]);
        out[base + (size_t)(y0 + ty) * WW + x0 + tx + 16]      = sigmoidf_(acc[1][o]);
        out[base + (size_t)(y0 + ty + 16) * WW + x0 + tx]      = sigmoidf_(acc[2][o]);
        out[base + (size_t)(y0 + ty + 16) * WW + x0 + tx + 16] = sigmoidf_(acc[3][o]);
    }
}

// ---------------------------------------------------------------------------
// fused head: per-pixel 190->64 (relu) ->1 (sigmoid) and 190->4 + softmax/sig.
// quality_input read virtually from the three d_out slabs.
// grid 1024, block 256
// ---------------------------------------------------------------------------
__global__ void head_kernel(const float* __restrict__ out_ro,
                            float* __restrict__ out,
                            const float* __restrict__ w1,
                            const float* __restrict__ b1,
                            const float* __restrict__ w2,
                            const float* __restrict__ b2,
                            const float* __restrict__ wc,
                            const float* __restrict__ bc) {
    __shared__ float s_w1[19 * 64];
    __shared__ float s_cls[QCIN * 4];   // [c][4]
    __shared__ float s_w2[64];
    __shared__ float s_b1[64];
    int tid = threadIdx.x;

    for (int i = tid; i < QCIN * 4; i += 256) {
        int c = i >> 2, o = i & 3;
        s_cls[i] = wc[o * QCIN + c];
    }
    if (tid < 64) { s_w2[tid] = w2[tid]; s_b1[tid] = b1[tid]; }

    int p = blockIdx.x * 256 + tid;
    int b = p >> 16, pix = p & 65535;

    const float* featp = out_ro + FEAT_OFF + ((size_t)(b * C2)) * HW + pix;
    const float* amp   = out_ro + AM_OFF + ((size_t)(b * NPAT)) * HW + pix;
    const float* anp   = out_ro + ANM_OFF + ((size_t)(b * NANOM)) * HW + pix;

    float acc[64];
#pragma unroll
    for (int o = 0; o < 64; ++o) acc[o] = 0.f;
    float cacc[4] = {0.f, 0.f, 0.f, 0.f};

    for (int ch = 0; ch < 10; ++ch) {
        int cbase = ch * 19;
        __syncthreads();
        for (int i = tid; i < 19 * 64; i += 256) {
            int j = i >> 6, o = i & 63;
            s_w1[i] = w1[o * QCIN + cbase + j];
        }
        __syncthreads();
#pragma unroll
        for (int j = 0; j < 19; ++j) {
            int c = cbase + j;
            float v;
            if (c < C2)             v = featp[(size_t)c * HW];
            else if (c < C2 + NPAT) v = amp[(size_t)(c - C2) * HW];
            else                    v = anp[(size_t)(c - C2 - NPAT) * HW];
            const float* wp = &s_w1[j * 64];
#pragma unroll
            for (int o = 0; o < 64; ++o) acc[o] = fmaf(v, wp[o], acc[o]);
            const float* cp = &s_cls[c * 4];
            cacc[0] = fmaf(v, cp[0], cacc[0]);
            cacc[1] = fmaf(v, cp[1], cacc[1]);
            cacc[2] = fmaf(v, cp[2], cacc[2]);
            cacc[3] = fmaf(v, cp[3], cacc[3]);
        }
    }

    float qs = 0.f;
#pragma unroll
    for (int o = 0; o < 64; ++o) {
        float q = fmaxf(acc[o] + s_b1[o], 0.f);
        qs = fmaf(q, s_w2[o], qs);
    }
    float quality = sigmoidf_(qs + b2[0]);

    float c0 = cacc[0] + bc[0];
    float c1 = cacc[1] + bc[1];
    float c2 = cacc[2] + bc[2];
    float c3 = cacc[3] + bc[3];
    float m = fmaxf(c0, fmaxf(c1, c2));
    float e0 = __expf(c0 - m), e1 = __expf(c1 - m), e2 = __expf(c2 - m);
    float inv = 1.f / (e0 + e1 + e2);

    size_t pb = (size_t)b * HW + pix;
    out[RL_OFF + ((size_t)(b * 3)) * HW + pix]     = c0;
    out[RL_OFF + ((size_t)(b * 3 + 1)) * HW + pix] = c1;
    out[RL_OFF + ((size_t)(b * 3 + 2)) * HW + pix] = c2;
    out[AL_OFF + pb] = c3;
    out[QS_OFF + pb] = quality;
    out[RP_OFF + ((size_t)(b * 3)) * HW + pix]     = e0 * inv;
    out[RP_OFF + ((size_t)(b * 3 + 1)) * HW + pix] = e1 * inv;
    out[RP_OFF + ((size_t)(b * 3 + 2)) * HW + pix] = e2 * inv;
    out[AP_OFF + pb] = sigmoidf_(c3);
}

// ---------------------------------------------------------------------------
extern "C" void kernel_launch(void* const* d_in, const int* in_sizes, int n_in,
                              void* d_out, int out_size) {
    (void)in_sizes; (void)n_in; (void)out_size;
    const float* x       = (const float*)d_in[0];
    const float* conv1_w = (const float*)d_in[1];
    const float* conv1_b = (const float*)d_in[2];
    const float* bn1_g   = (const float*)d_in[3];
    const float* bn1_b   = (const float*)d_in[4];
    const float* conv2_w = (const float*)d_in[5];
    const float* conv2_b = (const float*)d_in[6];
    const float* bn2_g   = (const float*)d_in[7];
    const float* bn2_b   = (const float*)d_in[8];
    const float* core_p  = (const float*)d_in[9];
    const float* clad_p  = (const float*)d_in[10];
    const float* ferr_p  = (const float*)d_in[11];
    const float* anom_p  = (const float*)d_in[12];
    const float* qa1_w   = (const float*)d_in[13];
    const float* qa1_b   = (const float*)d_in[14];
    const float* qa2_w   = (const float*)d_in[15];
    const float* qa2_b   = (const float*)d_in[16];
    const float* cls_w   = (const float*)d_in[17];
    const float* cls_b   = (const float*)d_in[18];
    float* out = (float*)d_out;

    // matcher weight pack (independent of conv chain; same-stream ordering ok)
    pack_mw_kernel<<<(64 * C2 * 9 + 255) / 256, 256>>>(core_p, clad_p, ferr_p, anom_p);

    // conv1 -> g_h1
    conv1_kernel<<<dim3(8, 16, BATCH * 4), 256>>>(x, conv1_w, conv1_b);
    // bn1 stats -> affine
    stats_kernel<<<C1, 256>>>(0, bn1_g, bn1_b);
    // conv2 (bn1+relu fused on load) -> g_feat
    conv2_kernel<<<dim3(8, 8, BATCH * 8), 256>>>(conv2_w, conv2_b);
    // bn2 stats -> affine
    stats_kernel<<<C2, 256>>>(1, bn2_g, bn2_b);
    // bn2+relu -> d_out features slab
    bn2_kernel<<<(BATCH * C2 * HW / 4) / 256, 256>>>((float4*)out);
    // matcher conv (sigmoid) -> all_matches / anomaly_matches slabs
    matcher_kernel<<<dim3(8, 8, BATCH * 4), 256>>>(out, out);
    // fused 1x1 head -> remaining 6 output slabs
    head_kernel<<<(BATCH * HW) / 256, 256>>>(out, out, qa1_w, qa1_b, qa2_w, qa2_b,
                                             cls_w, cls_b);
}

// round 3
// speedup vs baseline: 1.9029x; 1.9029x over previous
#include <cuda_runtime.h>
#include <math.h>
#include <stdint.h>

#define BATCH 4
#define HH 256
#define WW 256
#define HW 65536
#define C1 64
#define C2 128
#define NPAT 30
#define NANOM 32
#define QCIN 190

// d_out element offsets (outputs concatenated in reference return order)
#define FEAT_OFF 0UL
#define RL_OFF   33554432UL
#define AL_OFF   34340864UL
#define AM_OFF   34603008UL
#define ANM_OFF  42467328UL
#define QS_OFF   50855936UL
#define RP_OFF   51118080UL
#define AP_OFF   51904512UL

// ---------------------------------------------------------------------------
// device globals (no allocations allowed)
// ---------------------------------------------------------------------------
__device__ float  g_h1n[BATCH * HW * C1];     // conv1 out, NHWC, pre-bn
__device__ float  g_feat[BATCH * HW * C2];    // conv2 out, NHWC, pre-bn (incl bias)
__device__ float  g_stats1[2 * C1];           // [a | s] affine for bn1
__device__ float  g_stats2[2 * C2];           // [a | s] affine for bn2
__device__ float  g_w2p[9 * 2 * 128 * 32];    // conv2 weights packed [s][cc][oc(128)][k(32)], tf32
__device__ float  g_mwp[9 * 4 * 64 * 32];     // matcher weights packed [s][cc][oc(64)][k(32)], tf32
__device__ double g_psum[128 * 512];          // stats partials
__device__ double g_psq[128 * 512];

__device__ __forceinline__ float sigmoidf_(float v) {
    return 1.f / (1.f + __expf(-v));
}
__device__ __forceinline__ float to_tf32(float v) {
    uint32_t r;
    asm("cvt.rna.tf32.f32 %0, %1;" : "=r"(r) : "f"(v));
    return __uint_as_float(r);
}
__device__ __forceinline__ void mma_tf32(float* c, const uint32_t* a, uint32_t b0, uint32_t b1) {
    asm volatile(
        "mma.sync.aligned.m16n8k8.row.col.f32.tf32.tf32.f32 "
        "{%0,%1,%2,%3}, {%4,%5,%6,%7}, {%8,%9}, {%0,%1,%2,%3};"
        : "+f"(c[0]), "+f"(c[1]), "+f"(c[2]), "+f"(c[3])
        : "r"(a[0]), "r"(a[1]), "r"(a[2]), "r"(a[3]), "r"(b0), "r"(b1));
}

// ---------------------------------------------------------------------------
// conv1: 3 -> 64, 3x3 pad 1, bias. FFMA, NHWC output.
// grid (8, 16, BATCH*4), block 256
// ---------------------------------------------------------------------------
__global__ void conv1_kernel(const float* __restrict__ x,
                             const float* __restrict__ w,
                             const float* __restrict__ bias) {
    __shared__ float s_in[3][18][34];
    __shared__ float s_w[27 * 16];
    int tid = threadIdx.x;
    int bx = blockIdx.x, by = blockIdx.y;
    int b = blockIdx.z >> 2, g = blockIdx.z & 3;

    for (int i = tid; i < 3 * 18 * 34; i += 256) {
        int ci = i / 612;
        int r = (i % 612) / 34;
        int c = i % 34;
        int y = by * 16 - 1 + r, xx = bx * 32 - 1 + c;
        float v = 0.f;
        if (y >= 0 && y < HH && xx >= 0 && xx < WW)
            v = x[((size_t)(b * 3 + ci)) * HW + (size_t)y * WW + xx];
        s_in[ci][r][c] = v;
    }
    for (int i = tid; i < 27 * 16; i += 256) {
        int o = i & 15, rest = i >> 4;
        s_w[i] = w[(g * 16 + o) * 27 + rest];
    }
    __syncthreads();

    int tx = tid & 15, ty = tid >> 4;
    float acc0[16], acc1[16];
#pragma unroll
    for (int o = 0; o < 16; ++o) {
        float bb = bias[g * 16 + o];
        acc0[o] = bb; acc1[o] = bb;
    }
#pragma unroll
    for (int ci = 0; ci < 3; ++ci)
#pragma unroll
        for (int k = 0; k < 9; ++k) {
            int ky = k / 3, kx = k % 3;
            float v0 = s_in[ci][ty + ky][tx + kx];
            float v1 = s_in[ci][ty + ky][tx + 16 + kx];
            const float* wp = &s_w[(ci * 9 + k) * 16];
#pragma unroll
            for (int o = 0; o < 16; ++o) {
                float ww = wp[o];
                acc0[o] = fmaf(v0, ww, acc0[o]);
                acc1[o] = fmaf(v1, ww, acc1[o]);
            }
        }
    int gy = by * 16 + ty, gx = bx * 32 + tx;
    size_t p0 = ((size_t)((b * HH + gy) * WW + gx)) * C1 + g * 16;
    size_t p1 = ((size_t)((b * HH + gy) * WW + gx + 16)) * C1 + g * 16;
#pragma unroll
    for (int o = 0; o < 16; ++o) {
        g_h1n[p0 + o] = acc0[o];
        g_h1n[p1 + o] = acc1[o];
    }
}

// ---------------------------------------------------------------------------
// batchnorm stats, two-phase deterministic, over NHWC tensor [262144, C]
// ---------------------------------------------------------------------------
template<int C>
__global__ void stats_p1(const float* __restrict__ src) {
    __shared__ double ss[256], sq[256];
    const int ngrp = 256 / C;
    int g = blockIdx.x, tid = threadIdx.x;
    int ch = tid % C, grp = tid / C;
    size_t p0 = (size_t)g * 512;
    double s = 0.0, q = 0.0;
    for (int i = grp; i < 512; i += ngrp) {
        double v = (double)src[(p0 + i) * C + ch];
        s += v; q += v * v;
    }
    ss[tid] = s; sq[tid] = q;
    __syncthreads();
    if (grp == 0) {
#pragma unroll
        for (int k = 1; k < ngrp; ++k) { s += ss[ch + k * C]; q += sq[ch + k * C]; }
        g_psum[ch * 512 + g] = s;
        g_psq[ch * 512 + g] = q;
    }
}

template<int C>
__global__ void stats_p2(const float* __restrict__ gamma,
                         const float* __restrict__ beta,
                         float* __restrict__ statsOut) {
    __shared__ double ss[256], sq[256];
    int c = blockIdx.x, tid = threadIdx.x;
    double s = g_psum[c * 512 + tid] + g_psum[c * 512 + 256 + tid];
    double q = g_psq[c * 512 + tid] + g_psq[c * 512 + 256 + tid];
    ss[tid] = s; sq[tid] = q;
    __syncthreads();
    for (int st = 128; st > 0; st >>= 1) {
        if (tid < st) { ss[tid] += ss[tid + st]; sq[tid] += sq[tid + st]; }
        __syncthreads();
    }
    if (tid == 0) {
        double n = (double)BATCH * (double)HW;
        double mean = ss[0] / n;
        double var = sq[0] / n - mean * mean;
        double a = (double)gamma[c] / sqrt(var + 1e-5);
        statsOut[c] = (float)a;
        statsOut[C + c] = (float)((double)beta[c] - mean * a);
    }
}

// ---------------------------------------------------------------------------
// weight packing (values pre-rounded to tf32)
// ---------------------------------------------------------------------------
__global__ void pack_w2_kernel(const float* __restrict__ w2) {
    int i = blockIdx.x * 256 + threadIdx.x;
    if (i >= 9 * 2 * 128 * 32) return;
    int k = i & 31, oc = (i >> 5) & 127, cc = (i >> 12) & 1, s = i >> 13;
    g_w2p[i] = to_tf32(w2[oc * 576 + (cc * 32 + k) * 9 + s]);
}

__global__ void pack_mw_kernel(const float* __restrict__ core,
                               const float* __restrict__ clad,
                               const float* __restrict__ ferr,
                               const float* __restrict__ anom) {
    int i = blockIdx.x * 256 + threadIdx.x;
    if (i >= 9 * 4 * 64 * 32) return;
    int k = i & 31, oc = (i >> 5) & 63, cc = (i >> 11) & 3, s = i >> 13;
    int ci = cc * 32 + k;
    float v = 0.f;
    if (oc < 10)      v = core[oc * 1152 + ci * 9 + s];
    else if (oc < 20) v = clad[(oc - 10) * 1152 + ci * 9 + s];
    else if (oc < 30) v = ferr[(oc - 20) * 1152 + ci * 9 + s];
    else if (oc < 62) v = anom[(oc - 30) * 1152 + ci * 9 + s];
    g_mwp[i] = to_tf32(v);
}

// ---------------------------------------------------------------------------
// tf32 mma.sync implicit-GEMM conv (9 shifted 1x1 GEMMs over NHWC input).
// Template: MW warps along M (M = MW*32), NW = 8/MW warps along N
// (NTILE = NW*64). K accumulated over 9 shifts x NCC chunks of 32 channels.
// Double-buffered smem, stride-36 layout (conflict-free fragment loads).
// EPI 0: +bias -> NHWC out.  EPI 1: sigmoid -> NCHW match slabs (oc<62).
// grid (256*NTILE/256 per row handled by x, y=row, z=batch), block 256.
// ---------------------------------------------------------------------------
template<int MW, int NCC, bool AFF, int EPI>
__global__ __launch_bounds__(256)
void gemm_conv(const float* __restrict__ src,
               const float* __restrict__ wpack,
               const float* __restrict__ stats,
               const float* __restrict__ bias,
               float* __restrict__ out) {
    constexpr int M = MW * 32;
    constexpr int NW = 8 / MW;
    constexpr int NTILE = NW * 64;
    constexpr int CIN = NCC * 32;
    constexpr int NCHUNK = 9 * NCC;
    constexpr int ASZ = M * 36;        // floats, one buffer
    constexpr int BSZ = NTILE * 36;
    constexpr int NA4 = M / 32;        // float4 loads per thread (A)
    constexpr int NB4 = NTILE / 32;    // float4 loads per thread (B)

    extern __shared__ float dsm[];     // [2*ASZ | 2*BSZ]
    __shared__ float s_a[CIN], s_s[CIN];

    int tid = threadIdx.x;
    int warp = tid >> 5, lane = tid & 31;
    int warpM = warp % MW, warpN = warp / MW;
    int lr = lane >> 2, lc = lane & 3;
    int j = tid & 7;                   // k-group of 4 within 32-chunk
    int pr = tid >> 3;                 // row subindex 0..31
    int x0 = blockIdx.x * NTILE;
    int y = blockIdx.y, b = blockIdx.z;

    if (AFF) {
        if (tid < CIN) { s_a[tid] = stats[tid]; s_s[tid] = stats[CIN + tid]; }
    }

    float4 rA[NA4], rB[NB4];

    // ---- chunk loader: gmem -> regs ----
    auto load_regs = [&](int ic) {
        int s = ic / NCC, cc = ic % NCC;
        int ky = s / 3, kx = s % 3;
        int yy = y + ky - 1;
        bool yok = (unsigned)yy < 256u;
        const float* srow = src + ((size_t)((b * 256 + (yok ? yy : 0)) * 256)) * CIN;
        int ch0 = cc * 32 + j * 4;
#pragma unroll
        for (int it = 0; it < NB4; ++it) {
            int px = pr + it * 32;
            int xx = x0 + px + kx - 1;
            float4 v = make_float4(0.f, 0.f, 0.f, 0.f);
            if (yok && (unsigned)xx < 256u) {
                v = *(const float4*)&srow[(size_t)xx * CIN + ch0];
                if (AFF) {
                    v.x = fmaxf(fmaf(s_a[ch0 + 0], v.x, s_s[ch0 + 0]), 0.f);
                    v.y = fmaxf(fmaf(s_a[ch0 + 1], v.y, s_s[ch0 + 1]), 0.f);
                    v.z = fmaxf(fmaf(s_a[ch0 + 2], v.z, s_s[ch0 + 2]), 0.f);
                    v.w = fmaxf(fmaf(s_a[ch0 + 3], v.w, s_s[ch0 + 3]), 0.f);
                }
                v.x = to_tf32(v.x); v.y = to_tf32(v.y);
                v.z = to_tf32(v.z); v.w = to_tf32(v.w);
            }
            rB[it] = v;
        }
        const float* wp = wpack + (size_t)ic * (M * 32);
#pragma unroll
        for (int it = 0; it < NA4; ++it) {
            int oc = pr + it * 32;
            rA[it] = *(const float4*)&wp[oc * 32 + j * 4];
        }
    };
    auto store_smem = [&](int sel) {
        float* As = dsm + sel * ASZ;
        float* Bs = dsm + 2 * ASZ + sel * BSZ;
#pragma unroll
        for (int it = 0; it < NB4; ++it) {
            int px = pr + it * 32;
            float* p = &Bs[px * 36 + j * 4];
            p[0] = rB[it].x; p[1] = rB[it].y; p[2] = rB[it].z; p[3] = rB[it].w;
        }
#pragma unroll
        for (int it = 0; it < NA4; ++it) {
            int oc = pr + it * 32;
            float* p = &As[oc * 36 + j * 4];
            p[0] = rA[it].x; p[1] = rA[it].y; p[2] = rA[it].z; p[3] = rA[it].w;
        }
    };

    float c[2][8][4];
#pragma unroll
    for (int fm = 0; fm < 2; ++fm)
#pragma unroll
        for (int fn = 0; fn < 8; ++fn)
#pragma unroll
            for (int t = 0; t < 4; ++t) c[fm][fn][t] = 0.f;

    // prologue
    __syncthreads();       // s_a/s_s ready
    load_regs(0);
    store_smem(0);
    __syncthreads();

    for (int ic = 0; ic < NCHUNK; ++ic) {
        int sel = ic & 1;
        if (ic + 1 < NCHUNK) load_regs(ic + 1);

        const float* As = dsm + sel * ASZ;
        const float* Bs = dsm + 2 * ASZ + sel * BSZ;
#pragma unroll
        for (int ks = 0; ks < 4; ++ks) {
            int kq = ks * 8 + lc;
            uint32_t a[2][4];
#pragma unroll
            for (int fm = 0; fm < 2; ++fm) {
                int r0 = warpM * 32 + fm * 16 + lr;
                a[fm][0] = __float_as_uint(As[r0 * 36 + kq]);
                a[fm][1] = __float_as_uint(As[(r0 + 8) * 36 + kq]);
                a[fm][2] = __float_as_uint(As[r0 * 36 + kq + 4]);
                a[fm][3] = __float_as_uint(As[(r0 + 8) * 36 + kq + 4]);
            }
#pragma unroll
            for (int fn = 0; fn < 8; ++fn) {
                int n = warpN * 64 + fn * 8 + lr;
                uint32_t b0 = __float_as_uint(Bs[n * 36 + kq]);
                uint32_t b1 = __float_as_uint(Bs[n * 36 + kq + 4]);
                mma_tf32(c[0][fn], a[0], b0, b1);
                mma_tf32(c[1][fn], a[1], b0, b1);
            }
        }

        if (ic + 1 < NCHUNK) {
            __syncthreads();           // everyone done reading buf (ic+1)&1
            store_smem((ic + 1) & 1);
            __syncthreads();
        }
    }

    // ---- epilogue ----
    if (EPI == 0) {
#pragma unroll
        for (int fm = 0; fm < 2; ++fm) {
            int m0 = warpM * 32 + fm * 16 + lr;
            float bv0 = bias[m0], bv1 = bias[m0 + 8];
#pragma unroll
            for (int fn = 0; fn < 8; ++fn) {
                int px = x0 + warpN * 64 + fn * 8 + lc * 2;
                float* p = out + ((size_t)((b * 256 + y) * 256 + px)) * 128;
                p[m0]           = c[fm][fn][0] + bv0;
                p[128 + m0]     = c[fm][fn][1] + bv0;
                p[m0 + 8]       = c[fm][fn][2] + bv1;
                p[128 + m0 + 8] = c[fm][fn][3] + bv1;
            }
        }
    } else {
#pragma unroll
        for (int fm = 0; fm < 2; ++fm) {
            int m0 = warpM * 32 + fm * 16 + lr;
            int m1 = m0 + 8;
#pragma unroll
            for (int fn = 0; fn < 8; ++fn) {
                int px = x0 + warpN * 64 + fn * 8 + lc * 2;
                size_t rowoff = (size_t)y * 256 + px;
                if (m0 < 62) {
                    size_t base = (m0 < NPAT)
                        ? AM_OFF + ((size_t)(b * NPAT + m0)) * HW
                        : ANM_OFF + ((size_t)(b * NANOM + (m0 - NPAT))) * HW;
                    float2 v = make_float2(sigmoidf_(c[fm][fn][0]), sigmoidf_(c[fm][fn][1]));
                    *(float2*)&out[base + rowoff] = v;
                }
                if (m1 < 62) {
                    size_t base = (m1 < NPAT)
                        ? AM_OFF + ((size_t)(b * NPAT + m1)) * HW
                        : ANM_OFF + ((size_t)(b * NANOM + (m1 - NPAT))) * HW;
                    float2 v = make_float2(sigmoidf_(c[fm][fn][2]), sigmoidf_(c[fm][fn][3]));
                    *(float2*)&out[base + rowoff] = v;
                }
            }
        }
    }
}

// ---------------------------------------------------------------------------
// bn2 + relu: g_feat NHWC -> d_out features NCHW (smem tile transpose)
// grid (4, 256, BATCH), block 256.
// ---------------------------------------------------------------------------
__global__ void bn2t_kernel(float* __restrict__ out) {
    __shared__ float s_t[64][129];
    __shared__ float s_a[128], s_s[128];
    int tid = threadIdx.x;
    int x0 = blockIdx.x * 64, y = blockIdx.y, b = blockIdx.z;

    if (tid < 128) { s_a[tid] = g_stats2[tid]; s_s[tid] = g_stats2[128 + tid]; }
    __syncthreads();

    const float* src = g_feat + ((size_t)(b * 256 + y) * 256 + x0) * 128;
#pragma unroll
    for (int i = 0; i < 32; ++i) {
        int idx = tid + i * 256;
        int px = idx >> 7, ch = idx & 127;
        float v = src[(size_t)px * 128 + ch];
        s_t[px][ch] = fmaxf(fmaf(s_a[ch], v, s_s[ch]), 0.f);
    }
    __syncthreads();
#pragma unroll
    for (int i = 0; i < 32; ++i) {
        int idx = tid + i * 256;
        int ch = idx >> 6, px = idx & 63;
        out[FEAT_OFF + ((size_t)(b * 128 + ch)) * HW + (size_t)y * 256 + x0 + px] = s_t[px][ch];
    }
}

// ---------------------------------------------------------------------------
// fused head: per-pixel 190->64 (relu) ->1 (sigmoid) and 190->4 + softmax/sig.
// ---------------------------------------------------------------------------
__global__ void head_kernel(const float* __restrict__ out_ro,
                            float* __restrict__ out,
                            const float* __restrict__ w1,
                            const float* __restrict__ b1,
                            const float* __restrict__ w2,
                            const float* __restrict__ b2,
                            const float* __restrict__ wc,
                            const float* __restrict__ bc) {
    __shared__ float s_w1[19 * 64];
    __shared__ float s_cls[QCIN * 4];
    __shared__ float s_w2[64];
    __shared__ float s_b1[64];
    int tid = threadIdx.x;

    for (int i = tid; i < QCIN * 4; i += 256) {
        int c = i >> 2, o = i & 3;
        s_cls[i] = wc[o * QCIN + c];
    }
    if (tid < 64) { s_w2[tid] = w2[tid]; s_b1[tid] = b1[tid]; }

    int p = blockIdx.x * 256 + tid;
    int b = p >> 16, pix = p & 65535;

    const float* featp = out_ro + FEAT_OFF + ((size_t)(b * C2)) * HW + pix;
    const float* amp   = out_ro + AM_OFF + ((size_t)(b * NPAT)) * HW + pix;
    const float* anp   = out_ro + ANM_OFF + ((size_t)(b * NANOM)) * HW + pix;

    float acc[64];
#pragma unroll
    for (int o = 0; o < 64; ++o) acc[o] = 0.f;
    float cacc[4] = {0.f, 0.f, 0.f, 0.f};

    for (int ch = 0; ch < 10; ++ch) {
        int cbase = ch * 19;
        __syncthreads();
        for (int i = tid; i < 19 * 64; i += 256) {
            int jj = i >> 6, o = i & 63;
            s_w1[i] = w1[o * QCIN + cbase + jj];
        }
        __syncthreads();
#pragma unroll
        for (int jj = 0; jj < 19; ++jj) {
            int c = cbase + jj;
            float v;
            if (c < C2)             v = featp[(size_t)c * HW];
            else if (c < C2 + NPAT) v = amp[(size_t)(c - C2) * HW];
            else                    v = anp[(size_t)(c - C2 - NPAT) * HW];
            const float* wp = &s_w1[jj * 64];
#pragma unroll
            for (int o = 0; o < 64; ++o) acc[o] = fmaf(v, wp[o], acc[o]);
            const float* cp = &s_cls[c * 4];
            cacc[0] = fmaf(v, cp[0], cacc[0]);
            cacc[1] = fmaf(v, cp[1], cacc[1]);
            cacc[2] = fmaf(v, cp[2], cacc[2]);
            cacc[3] = fmaf(v, cp[3], cacc[3]);
        }
    }

    float qs = 0.f;
#pragma unroll
    for (int o = 0; o < 64; ++o) {
        float q = fmaxf(acc[o] + s_b1[o], 0.f);
        qs = fmaf(q, s_w2[o], qs);
    }
    float quality = sigmoidf_(qs + b2[0]);

    float c0 = cacc[0] + bc[0];
    float c1 = cacc[1] + bc[1];
    float c2 = cacc[2] + bc[2];
    float c3 = cacc[3] + bc[3];
    float m = fmaxf(c0, fmaxf(c1, c2));
    float e0 = __expf(c0 - m), e1 = __expf(c1 - m), e2 = __expf(c2 - m);
    float inv = 1.f / (e0 + e1 + e2);

    size_t pb = (size_t)b * HW + pix;
    out[RL_OFF + ((size_t)(b * 3)) * HW + pix]     = c0;
    out[RL_OFF + ((size_t)(b * 3 + 1)) * HW + pix] = c1;
    out[RL_OFF + ((size_t)(b * 3 + 2)) * HW + pix] = c2;
    out[AL_OFF + pb] = c3;
    out[QS_OFF + pb] = quality;
    out[RP_OFF + ((size_t)(b * 3)) * HW + pix]     = e0 * inv;
    out[RP_OFF + ((size_t)(b * 3 + 1)) * HW + pix] = e1 * inv;
    out[RP_OFF + ((size_t)(b * 3 + 2)) * HW + pix] = e2 * inv;
    out[AP_OFF + pb] = sigmoidf_(c3);
}

// ---------------------------------------------------------------------------
extern "C" void kernel_launch(void* const* d_in, const int* in_sizes, int n_in,
                              void* d_out, int out_size) {
    (void)in_sizes; (void)n_in; (void)out_size;
    const float* x       = (const float*)d_in[0];
    const float* conv1_w = (const float*)d_in[1];
    const float* conv1_b = (const float*)d_in[2];
    const float* bn1_g   = (const float*)d_in[3];
    const float* bn1_b   = (const float*)d_in[4];
    const float* conv2_w = (const float*)d_in[5];
    const float* conv2_b = (const float*)d_in[6];
    const float* bn2_g   = (const float*)d_in[7];
    const float* bn2_b   = (const float*)d_in[8];
    const float* core_p  = (const float*)d_in[9];
    const float* clad_p  = (const float*)d_in[10];
    const float* ferr_p  = (const float*)d_in[11];
    const float* anom_p  = (const float*)d_in[12];
    const float* qa1_w   = (const float*)d_in[13];
    const float* qa1_b   = (const float*)d_in[14];
    const float* qa2_w   = (const float*)d_in[15];
    const float* qa2_b   = (const float*)d_in[16];
    const float* cls_w   = (const float*)d_in[17];
    const float* cls_b   = (const float*)d_in[18];
    float* out = (float*)d_out;

    // conv2: MW=4 (M=128), NCC=2, NTILE=128 -> smem (2*128*36 + 2*128*36)*4 B
    const int smem_c2 = (2 * 128 * 36 + 2 * 128 * 36) * 4;      // 73728
    // matcher: MW=2 (M=64), NCC=4, NTILE=256 -> smem (2*64*36 + 2*256*36)*4 B
    const int smem_mt = (2 * 64 * 36 + 2 * 256 * 36) * 4;       // 92160
    cudaFuncSetAttribute(gemm_conv<4, 2, true, 0>,
                         cudaFuncAttributeMaxDynamicSharedMemorySize, smem_c2);
    cudaFuncSetAttribute(gemm_conv<2, 4, true, 1>,
                         cudaFuncAttributeMaxDynamicSharedMemorySize, smem_mt);

    float* d_stats1; cudaGetSymbolAddress((void**)&d_stats1, g_stats1);
    float* d_stats2; cudaGetSymbolAddress((void**)&d_stats2, g_stats2);
    float* d_h1n;    cudaGetSymbolAddress((void**)&d_h1n, g_h1n);
    float* d_feat;   cudaGetSymbolAddress((void**)&d_feat, g_feat);
    float* d_w2p;    cudaGetSymbolAddress((void**)&d_w2p, g_w2p);
    float* d_mwp;    cudaGetSymbolAddress((void**)&d_mwp, g_mwp);

    // weight packing (independent)
    pack_w2_kernel<<<(9 * 2 * 128 * 32 + 255) / 256, 256>>>(conv2_w);
    pack_mw_kernel<<<(9 * 4 * 64 * 32 + 255) / 256, 256>>>(core_p, clad_p, ferr_p, anom_p);

    // conv1 -> h1 (NHWC, pre-bn)
    conv1_kernel<<<dim3(8, 16, BATCH * 4), 256>>>(x, conv1_w, conv1_b);
    // bn1 stats
    stats_p1<C1><<<512, 256>>>(d_h1n);
    stats_p2<C1><<<C1, 256>>>(bn1_g, bn1_b, d_stats1);
    // conv2 mma.sync tf32 (bn1+relu fused on load) -> g_feat NHWC
    gemm_conv<4, 2, true, 0><<<dim3(2, 256, BATCH), 256, smem_c2>>>(
        d_h1n, d_w2p, d_stats1, conv2_b, d_feat);
    // bn2 stats
    stats_p1<C2><<<512, 256>>>(d_feat);
    stats_p2<C2><<<C2, 256>>>(bn2_g, bn2_b, d_stats2);
    // bn2+relu transpose -> d_out features NCHW
    bn2t_kernel<<<dim3(4, 256, BATCH), 256>>>(out);
    // matcher mma.sync tf32 (bn2+relu fused on load, sigmoid epi) -> AM/ANM slabs
    gemm_conv<2, 4, true, 1><<<dim3(1, 256, BATCH), 256, smem_mt>>>(
        d_feat, d_mwp, d_stats2, nullptr, out);
    // fused 1x1 head -> remaining 6 output slabs
    head_kernel<<<(BATCH * HW) / 256, 256>>>(out, out, qa1_w, qa1_b, qa2_w, qa2_b,
                                             cls_w, cls_b);
}

// round 5
// speedup vs baseline: 2.2093x; 1.1610x over previous
#include <cuda_runtime.h>
#include <math.h>
#include <stdint.h>

#define BATCH 4
#define HH 256
#define WW 256
#define HW 65536
#define C1 64
#define C2 128
#define NPAT 30
#define NANOM 32
#define QCIN 190

// d_out element offsets (outputs concatenated in reference return order)
#define FEAT_OFF 0UL
#define RL_OFF   33554432UL
#define AL_OFF   34340864UL
#define AM_OFF   34603008UL
#define ANM_OFF  42467328UL
#define QS_OFF   50855936UL
#define RP_OFF   51118080UL
#define AP_OFF   51904512UL

// ---------------------------------------------------------------------------
// device globals (no allocations allowed)
// ---------------------------------------------------------------------------
__device__ float  g_h1n[BATCH * HW * C1];     // conv1 out NHWC; after apply1: tf32(relu(bn1))
__device__ float  g_feat[BATCH * HW * C2];    // conv2 out NHWC; after bn2t: tf32(relu(bn2))
__device__ float  g_stats1[2 * C1];           // [a | s] affine for bn1
__device__ float  g_stats2[2 * C2];           // [a | s] affine for bn2
__device__ float  g_w2p[9 * 2 * 128 * 32];    // conv2 weights packed [s][cc][oc(128)][k(32)], tf32
__device__ float  g_mwp[9 * 4 * 64 * 32];     // matcher weights packed [s][cc][oc(64)][k(32)], tf32
__device__ float  g_psumf[128 * 2048];        // stats partials (fp32)
__device__ float  g_psqf[128 * 2048];

__device__ __forceinline__ float sigmoidf_(float v) {
    return 1.f / (1.f + __expf(-v));
}
__device__ __forceinline__ float to_tf32(float v) {
    uint32_t r;
    asm("cvt.rna.tf32.f32 %0, %1;" : "=r"(r) : "f"(v));
    return __uint_as_float(r);
}
__device__ __forceinline__ void mma_tf32(float* c, const uint32_t* a, uint32_t b0, uint32_t b1) {
    asm volatile(
        "mma.sync.aligned.m16n8k8.row.col.f32.tf32.tf32.f32 "
        "{%0,%1,%2,%3}, {%4,%5,%6,%7}, {%8,%9}, {%0,%1,%2,%3};"
        : "+f"(c[0]), "+f"(c[1]), "+f"(c[2]), "+f"(c[3])
        : "r"(a[0]), "r"(a[1]), "r"(a[2]), "r"(a[3]), "r"(b0), "r"(b1));
}

// ---------------------------------------------------------------------------
// merged weight packing (values pre-rounded to tf32).  576 blocks.
// [0, 73728): conv2 pack   [73728, 147456): matcher pack
// ---------------------------------------------------------------------------
__global__ void pack_all_kernel(const float* __restrict__ w2,
                                const float* __restrict__ core,
                                const float* __restrict__ clad,
                                const float* __restrict__ ferr,
                                const float* __restrict__ anom) {
    int i = blockIdx.x * 256 + threadIdx.x;
    if (i < 9 * 2 * 128 * 32) {
        int k = i & 31, oc = (i >> 5) & 127, cc = (i >> 12) & 1, s = i >> 13;
        g_w2p[i] = to_tf32(w2[oc * 576 + (cc * 32 + k) * 9 + s]);
    } else {
        int m = i - 9 * 2 * 128 * 32;
        if (m >= 9 * 4 * 64 * 32) return;
        int k = m & 31, oc = (m >> 5) & 63, cc = (m >> 11) & 3, s = m >> 13;
        int ci = cc * 32 + k;
        float v = 0.f;
        if (oc < 10)      v = core[oc * 1152 + ci * 9 + s];
        else if (oc < 20) v = clad[(oc - 10) * 1152 + ci * 9 + s];
        else if (oc < 30) v = ferr[(oc - 20) * 1152 + ci * 9 + s];
        else if (oc < 62) v = anom[(oc - 30) * 1152 + ci * 9 + s];
        g_mwp[m] = to_tf32(v);
    }
}

// ---------------------------------------------------------------------------
// conv1: 3 -> 64, 3x3 pad 1, bias. FFMA, NHWC output.
// grid (8, 16, BATCH*4), block 256
// ---------------------------------------------------------------------------
__global__ void conv1_kernel(const float* __restrict__ x,
                             const float* __restrict__ w,
                             const float* __restrict__ bias) {
    __shared__ float s_in[3][18][34];
    __shared__ float s_w[27 * 16];
    int tid = threadIdx.x;
    int bx = blockIdx.x, by = blockIdx.y;
    int b = blockIdx.z >> 2, g = blockIdx.z & 3;

    for (int i = tid; i < 3 * 18 * 34; i += 256) {
        int ci = i / 612;
        int r = (i % 612) / 34;
        int c = i % 34;
        int y = by * 16 - 1 + r, xx = bx * 32 - 1 + c;
        float v = 0.f;
        if (y >= 0 && y < HH && xx >= 0 && xx < WW)
            v = x[((size_t)(b * 3 + ci)) * HW + (size_t)y * WW + xx];
        s_in[ci][r][c] = v;
    }
    for (int i = tid; i < 27 * 16; i += 256) {
        int o = i & 15, rest = i >> 4;
        s_w[i] = w[(g * 16 + o) * 27 + rest];
    }
    __syncthreads();

    int tx = tid & 15, ty = tid >> 4;
    float acc0[16], acc1[16];
#pragma unroll
    for (int o = 0; o < 16; ++o) {
        float bb = bias[g * 16 + o];
        acc0[o] = bb; acc1[o] = bb;
    }
#pragma unroll
    for (int ci = 0; ci < 3; ++ci)
#pragma unroll
        for (int k = 0; k < 9; ++k) {
            int ky = k / 3, kx = k % 3;
            float v0 = s_in[ci][ty + ky][tx + kx];
            float v1 = s_in[ci][ty + ky][tx + 16 + kx];
            const float* wp = &s_w[(ci * 9 + k) * 16];
#pragma unroll
            for (int o = 0; o < 16; ++o) {
                float ww = wp[o];
                acc0[o] = fmaf(v0, ww, acc0[o]);
                acc1[o] = fmaf(v1, ww, acc1[o]);
            }
        }
    int gy = by * 16 + ty, gx = bx * 32 + tx;
    size_t p0 = ((size_t)((b * HH + gy) * WW + gx)) * C1 + g * 16;
    size_t p1 = ((size_t)((b * HH + gy) * WW + gx + 16)) * C1 + g * 16;
#pragma unroll
    for (int o = 0; o < 16; ++o) {
        g_h1n[p0 + o] = acc0[o];
        g_h1n[p1 + o] = acc1[o];
    }
}

// ---------------------------------------------------------------------------
// batchnorm stats phase 1: fp32 partial sums over 128-pixel chunks.
// grid 2048, block 256. Deterministic (fixed tree per chunk).
// ---------------------------------------------------------------------------
template<int C>
__global__ void stats_p1(const float* __restrict__ src) {
    __shared__ float ss[256], sq[256];
    constexpr int NSUB = 256 / C;
    int blk = blockIdx.x, tid = threadIdx.x;
    int ch = tid % C, sub = tid / C;
    const float* p = src + (size_t)blk * 128 * C;
    float s = 0.f, q = 0.f;
    for (int i = sub; i < 128; i += NSUB) {
        float v = p[(size_t)i * C + ch];
        s += v;
        q = fmaf(v, v, q);
    }
    ss[tid] = s; sq[tid] = q;
    __syncthreads();
    if (sub == 0) {
#pragma unroll
        for (int k = 1; k < NSUB; ++k) { s += ss[ch + k * C]; q += sq[ch + k * C]; }
        g_psumf[ch * 2048 + blk] = s;
        g_psqf[ch * 2048 + blk] = q;
    }
}

// phase 2: reduce 2048 fp32 partials per channel in double. grid C, block 256.
template<int C>
__global__ void stats_p2(const float* __restrict__ gamma,
                         const float* __restrict__ beta,
                         float* __restrict__ statsOut) {
    __shared__ double ss[256], sq[256];
    int c = blockIdx.x, tid = threadIdx.x;
    double s = 0.0, q = 0.0;
#pragma unroll
    for (int k = 0; k < 8; ++k) {
        s += (double)g_psumf[c * 2048 + tid + k * 256];
        q += (double)g_psqf[c * 2048 + tid + k * 256];
    }
    ss[tid] = s; sq[tid] = q;
    __syncthreads();
    for (int st = 128; st > 0; st >>= 1) {
        if (tid < st) { ss[tid] += ss[tid + st]; sq[tid] += sq[tid + st]; }
        __syncthreads();
    }
    if (tid == 0) {
        double n = (double)BATCH * (double)HW;
        double mean = ss[0] / n;
        double var = sq[0] / n - mean * mean;
        double a = (double)gamma[c] / sqrt(var + 1e-5);
        statsOut[c] = (float)a;
        statsOut[C + c] = (float)((double)beta[c] - mean * a);
    }
}

// ---------------------------------------------------------------------------
// apply1: g_h1n <- tf32(relu(a*x+s)) in place (NHWC, C=64). float4.
// total float4 = BATCH*HW*C1/4 = 4194304  -> grid 16384, block 256.
// ---------------------------------------------------------------------------
__global__ void apply1_kernel() {
    int i = blockIdx.x * 256 + threadIdx.x;     // float4 index
    int ch0 = (i * 4) & 63;
    float4 v = ((const float4*)g_h1n)[i];
    v.x = to_tf32(fmaxf(fmaf(g_stats1[ch0 + 0], v.x, g_stats1[C1 + ch0 + 0]), 0.f));
    v.y = to_tf32(fmaxf(fmaf(g_stats1[ch0 + 1], v.y, g_stats1[C1 + ch0 + 1]), 0.f));
    v.z = to_tf32(fmaxf(fmaf(g_stats1[ch0 + 2], v.z, g_stats1[C1 + ch0 + 2]), 0.f));
    v.w = to_tf32(fmaxf(fmaf(g_stats1[ch0 + 3], v.w, g_stats1[C1 + ch0 + 3]), 0.f));
    ((float4*)g_h1n)[i] = v;
}

// ---------------------------------------------------------------------------
// tf32 mma.sync implicit-GEMM conv (9 shifted 1x1 GEMMs over NHWC input).
// Inputs are pre-rounded tf32 values (bn+relu pre-applied).  Double-buffered
// smem, row stride 40 words, permuted-k layout: within each 8-group,
// k -> (k&3)*2 + (k>>2), so every mma fragment load is one float2 and the
// fragment loads are bank-conflict-free.
// EPI 0: +bias -> NHWC out.  EPI 1: sigmoid -> NCHW match slabs (oc<62).
// ---------------------------------------------------------------------------
template<int MW, int NCC, int EPI>
__global__ __launch_bounds__(256, 2)
void gemm_conv(const float* __restrict__ src,
               const float* __restrict__ wpack,
               const float* __restrict__ bias,
               float* __restrict__ out) {
    constexpr int M = MW * 32;
    constexpr int NW = 8 / MW;
    constexpr int NTILE = NW * 64;
    constexpr int CIN = NCC * 32;
    constexpr int NCHUNK = 9 * NCC;
    constexpr int ROWW = 40;           // words per row (160B): conflict-free frags
    constexpr int ASZ = M * ROWW;
    constexpr int BSZ = NTILE * ROWW;
    constexpr int NA4 = M / 32;
    constexpr int NB4 = NTILE / 32;

    extern __shared__ float dsm[];     // [2*ASZ | 2*BSZ]

    int tid = threadIdx.x;
    int warp = tid >> 5, lane = tid & 31;
    int warpM = warp % MW, warpN = warp / MW;
    int lr = lane >> 2, lc = lane & 3;
    int j = tid & 7;                   // k-group of 4 within 32-chunk
    int pr = tid >> 3;                 // row subindex 0..31
    int x0 = blockIdx.x * NTILE;
    int y = blockIdx.y, b = blockIdx.z;

    float4 rA[NA4], rB[NB4];

    auto load_regs = [&](int ic) {
        int s = ic / NCC, cc = ic % NCC;
        int ky = s / 3, kx = s % 3;
        int yy = y + ky - 1;
        bool yok = (unsigned)yy < 256u;
        const float* srow = src + ((size_t)((b * 256 + (yok ? yy : 0)) * 256)) * CIN;
        int ch0 = cc * 32 + j * 4;
#pragma unroll
        for (int it = 0; it < NB4; ++it) {
            int px = pr + it * 32;
            int xx = x0 + px + kx - 1;
            float4 v = make_float4(0.f, 0.f, 0.f, 0.f);
            if (yok && (unsigned)xx < 256u)
                v = *(const float4*)&srow[(size_t)xx * CIN + ch0];
            rB[it] = v;
        }
        const float* wp = wpack + (size_t)ic * (M * 32);
#pragma unroll
        for (int it = 0; it < NA4; ++it) {
            int oc = pr + it * 32;
            rA[it] = *(const float4*)&wp[oc * 32 + j * 4];
        }
    };
    // permuted scatter: value k=j*4+i goes to col (j>>1)*8 + i*2 + (j&1)
    auto store_smem = [&](int sel) {
        float* As = dsm + sel * ASZ;
        float* Bs = dsm + 2 * ASZ + sel * BSZ;
        int colb = (j >> 1) * 8 + (j & 1);
#pragma unroll
        for (int it = 0; it < NB4; ++it) {
            float* p = &Bs[(pr + it * 32) * ROWW + colb];
            p[0] = rB[it].x; p[2] = rB[it].y; p[4] = rB[it].z; p[6] = rB[it].w;
        }
#pragma unroll
        for (int it = 0; it < NA4; ++it) {
            float* p = &As[(pr + it * 32) * ROWW + colb];
            p[0] = rA[it].x; p[2] = rA[it].y; p[4] = rA[it].z; p[6] = rA[it].w;
        }
    };

    float c[2][8][4];
#pragma unroll
    for (int fm = 0; fm < 2; ++fm)
#pragma unroll
        for (int fn = 0; fn < 8; ++fn)
#pragma unroll
            for (int t = 0; t < 4; ++t) c[fm][fn][t] = 0.f;

    load_regs(0);
    store_smem(0);
    __syncthreads();

    for (int ic = 0; ic < NCHUNK; ++ic) {
        int sel = ic & 1;
        if (ic + 1 < NCHUNK) load_regs(ic + 1);

        const float* As = dsm + sel * ASZ;
        const float* Bs = dsm + 2 * ASZ + sel * BSZ;
#pragma unroll
        for (int ks = 0; ks < 4; ++ks) {
            int col = ks * 8 + lc * 2;
            uint32_t a[2][4];
#pragma unroll
            for (int fm = 0; fm < 2; ++fm) {
                int r0 = warpM * 32 + fm * 16 + lr;
                float2 lo = *(const float2*)&As[r0 * ROWW + col];
                float2 hi = *(const float2*)&As[(r0 + 8) * ROWW + col];
                a[fm][0] = __float_as_uint(lo.x);
                a[fm][1] = __float_as_uint(hi.x);
                a[fm][2] = __float_as_uint(lo.y);
                a[fm][3] = __float_as_uint(hi.y);
            }
#pragma unroll
            for (int fn = 0; fn < 8; ++fn) {
                int n = warpN * 64 + fn * 8 + lr;
                float2 bb = *(const float2*)&Bs[n * ROWW + col];
                uint32_t b0 = __float_as_uint(bb.x);
                uint32_t b1 = __float_as_uint(bb.y);
                mma_tf32(c[0][fn], a[0], b0, b1);
                mma_tf32(c[1][fn], a[1], b0, b1);
            }
        }

        if (ic + 1 < NCHUNK) {
            __syncthreads();
            store_smem((ic + 1) & 1);
            __syncthreads();
        }
    }

    // ---- epilogue ----
    if (EPI == 0) {
#pragma unroll
        for (int fm = 0; fm < 2; ++fm) {
            int m0 = warpM * 32 + fm * 16 + lr;
            float bv0 = bias[m0], bv1 = bias[m0 + 8];
#pragma unroll
            for (int fn = 0; fn < 8; ++fn) {
                int px = x0 + warpN * 64 + fn * 8 + lc * 2;
                float* p = out + ((size_t)((b * 256 + y) * 256 + px)) * 128;
                p[m0]           = c[fm][fn][0] + bv0;
                p[128 + m0]     = c[fm][fn][1] + bv0;
                p[m0 + 8]       = c[fm][fn][2] + bv1;
                p[128 + m0 + 8] = c[fm][fn][3] + bv1;
            }
        }
    } else {
#pragma unroll
        for (int fm = 0; fm < 2; ++fm) {
            int m0 = warpM * 32 + fm * 16 + lr;
            int m1 = m0 + 8;
#pragma unroll
            for (int fn = 0; fn < 8; ++fn) {
                int px = x0 + warpN * 64 + fn * 8 + lc * 2;
                size_t rowoff = (size_t)y * 256 + px;
                if (m0 < 62) {
                    size_t base = (m0 < NPAT)
                        ? AM_OFF + ((size_t)(b * NPAT + m0)) * HW
                        : ANM_OFF + ((size_t)(b * NANOM + (m0 - NPAT))) * HW;
                    float2 v = make_float2(sigmoidf_(c[fm][fn][0]), sigmoidf_(c[fm][fn][1]));
                    *(float2*)&out[base + rowoff] = v;
                }
                if (m1 < 62) {
                    size_t base = (m1 < NPAT)
                        ? AM_OFF + ((size_t)(b * NPAT + m1)) * HW
                        : ANM_OFF + ((size_t)(b * NANOM + (m1 - NPAT))) * HW;
                    float2 v = make_float2(sigmoidf_(c[fm][fn][2]), sigmoidf_(c[fm][fn][3]));
                    *(float2*)&out[base + rowoff] = v;
                }
            }
        }
    }
}

// ---------------------------------------------------------------------------
// bn2 + relu: g_feat NHWC -> d_out features NCHW (fp32) AND writes the
// tf32-rounded value back to g_feat in place (matcher input).
// grid (4, 256, BATCH), block 256.
// ---------------------------------------------------------------------------
__global__ void bn2t_kernel(float* __restrict__ out) {
    __shared__ float s_t[64][129];
    __shared__ float s_a[128], s_s[128];
    int tid = threadIdx.x;
    int x0 = blockIdx.x * 64, y = blockIdx.y, b = blockIdx.z;

    if (tid < 128) { s_a[tid] = g_stats2[tid]; s_s[tid] = g_stats2[128 + tid]; }
    __syncthreads();

    float* src = g_feat + ((size_t)(b * 256 + y) * 256 + x0) * 128;
#pragma unroll
    for (int i = 0; i < 32; ++i) {
        int idx = tid + i * 256;
        int px = idx >> 7, ch = idx & 127;
        float v = src[(size_t)px * 128 + ch];
        v = fmaxf(fmaf(s_a[ch], v, s_s[ch]), 0.f);
        s_t[px][ch] = v;
        src[(size_t)px * 128 + ch] = to_tf32(v);
    }
    __syncthreads();
#pragma unroll
    for (int i = 0; i < 32; ++i) {
        int idx = tid + i * 256;
        int ch = idx >> 6, px = idx & 63;
        out[FEAT_OFF + ((size_t)(b * 128 + ch)) * HW + (size_t)y * 256 + x0 + px] = s_t[px][ch];
    }
}

// ---------------------------------------------------------------------------
// fused head: per-pixel 190->64 (relu) ->1 (sigmoid) and 190->4 + softmax/sig.
// ---------------------------------------------------------------------------
__global__ void head_kernel(const float* __restrict__ out_ro,
                            float* __restrict__ out,
                            const float* __restrict__ w1,
                            const float* __restrict__ b1,
                            const float* __restrict__ w2,
                            const float* __restrict__ b2,
                            const float* __restrict__ wc,
                            const float* __restrict__ bc) {
    __shared__ float s_w1[19 * 64];
    __shared__ float s_cls[QCIN * 4];
    __shared__ float s_w2[64];
    __shared__ float s_b1[64];
    int tid = threadIdx.x;

    for (int i = tid; i < QCIN * 4; i += 256) {
        int c = i >> 2, o = i & 3;
        s_cls[i] = wc[o * QCIN + c];
    }
    if (tid < 64) { s_w2[tid] = w2[tid]; s_b1[tid] = b1[tid]; }

    int p = blockIdx.x * 256 + tid;
    int b = p >> 16, pix = p & 65535;

    const float* featp = out_ro + FEAT_OFF + ((size_t)(b * C2)) * HW + pix;
    const float* amp   = out_ro + AM_OFF + ((size_t)(b * NPAT)) * HW + pix;
    const float* anp   = out_ro + ANM_OFF + ((size_t)(b * NANOM)) * HW + pix;

    float acc[64];
#pragma unroll
    for (int o = 0; o < 64; ++o) acc[o] = 0.f;
    float cacc[4] = {0.f, 0.f, 0.f, 0.f};

    for (int ch = 0; ch < 10; ++ch) {
        int cbase = ch * 19;
        __syncthreads();
        for (int i = tid; i < 19 * 64; i += 256) {
            int jj = i >> 6, o = i & 63;
            s_w1[i] = w1[o * QCIN + cbase + jj];
        }
        __syncthreads();
#pragma unroll
        for (int jj = 0; jj < 19; ++jj) {
            int c = cbase + jj;
            float v;
            if (c < C2)             v = featp[(size_t)c * HW];
            else if (c < C2 + NPAT) v = amp[(size_t)(c - C2) * HW];
            else                    v = anp[(size_t)(c - C2 - NPAT) * HW];
            const float* wp = &s_w1[jj * 64];
#pragma unroll
            for (int o = 0; o < 64; ++o) acc[o] = fmaf(v, wp[o], acc[o]);
            const float* cp = &s_cls[c * 4];
            cacc[0] = fmaf(v, cp[0], cacc[0]);
            cacc[1] = fmaf(v, cp[1], cacc[1]);
            cacc[2] = fmaf(v, cp[2], cacc[2]);
            cacc[3] = fmaf(v, cp[3], cacc[3]);
        }
    }

    float qs = 0.f;
#pragma unroll
    for (int o = 0; o < 64; ++o) {
        float q = fmaxf(acc[o] + s_b1[o], 0.f);
        qs = fmaf(q, s_w2[o], qs);
    }
    float quality = sigmoidf_(qs + b2[0]);

    float c0 = cacc[0] + bc[0];
    float c1 = cacc[1] + bc[1];
    float c2 = cacc[2] + bc[2];
    float c3 = cacc[3] + bc[3];
    float m = fmaxf(c0, fmaxf(c1, c2));
    float e0 = __expf(c0 - m), e1 = __expf(c1 - m), e2 = __expf(c2 - m);
    float inv = 1.f / (e0 + e1 + e2);

    size_t pb = (size_t)b * HW + pix;
    out[RL_OFF + ((size_t)(b * 3)) * HW + pix]     = c0;
    out[RL_OFF + ((size_t)(b * 3 + 1)) * HW + pix] = c1;
    out[RL_OFF + ((size_t)(b * 3 + 2)) * HW + pix] = c2;
    out[AL_OFF + pb] = c3;
    out[QS_OFF + pb] = quality;
    out[RP_OFF + ((size_t)(b * 3)) * HW + pix]     = e0 * inv;
    out[RP_OFF + ((size_t)(b * 3 + 1)) * HW + pix] = e1 * inv;
    out[RP_OFF + ((size_t)(b * 3 + 2)) * HW + pix] = e2 * inv;
    out[AP_OFF + pb] = sigmoidf_(c3);
}

// ---------------------------------------------------------------------------
extern "C" void kernel_launch(void* const* d_in, const int* in_sizes, int n_in,
                              void* d_out, int out_size) {
    (void)in_sizes; (void)n_in; (void)out_size;
    const float* x       = (const float*)d_in[0];
    const float* conv1_w = (const float*)d_in[1];
    const float* conv1_b = (const float*)d_in[2];
    const float* bn1_g   = (const float*)d_in[3];
    const float* bn1_b   = (const float*)d_in[4];
    const float* conv2_w = (const float*)d_in[5];
    const float* conv2_b = (const float*)d_in[6];
    const float* bn2_g   = (const float*)d_in[7];
    const float* bn2_b   = (const float*)d_in[8];
    const float* core_p  = (const float*)d_in[9];
    const float* clad_p  = (const float*)d_in[10];
    const float* ferr_p  = (const float*)d_in[11];
    const float* anom_p  = (const float*)d_in[12];
    const float* qa1_w   = (const float*)d_in[13];
    const float* qa1_b   = (const float*)d_in[14];
    const float* qa2_w   = (const float*)d_in[15];
    const float* qa2_b   = (const float*)d_in[16];
    const float* cls_w   = (const float*)d_in[17];
    const float* cls_b   = (const float*)d_in[18];
    float* out = (float*)d_out;

    // conv2: MW=4 (M=128, NTILE=128): smem 2*(128+128)*40*4 = 81920 B
    const int smem_c2 = 2 * (128 + 128) * 40 * 4;
    // matcher: MW=2 (M=64, NTILE=256): smem 2*(64+256)*40*4 = 102400 B
    const int smem_mt = 2 * (64 + 256) * 40 * 4;
    cudaFuncSetAttribute(gemm_conv<4, 2, 0>,
                         cudaFuncAttributeMaxDynamicSharedMemorySize, smem_c2);
    cudaFuncSetAttribute(gemm_conv<2, 4, 1>,
                         cudaFuncAttributeMaxDynamicSharedMemorySize, smem_mt);

    float* d_stats1; cudaGetSymbolAddress((void**)&d_stats1, g_stats1);
    float* d_stats2; cudaGetSymbolAddress((void**)&d_stats2, g_stats2);
    float* d_h1n;    cudaGetSymbolAddress((void**)&d_h1n, g_h1n);
    float* d_feat;   cudaGetSymbolAddress((void**)&d_feat, g_feat);
    float* d_w2p;    cudaGetSymbolAddress((void**)&d_w2p, g_w2p);
    float* d_mwp;    cudaGetSymbolAddress((void**)&d_mwp, g_mwp);

    // [0] weight packing
    pack_all_kernel<<<576, 256>>>(conv2_w, core_p, clad_p, ferr_p, anom_p);
    // [1] conv1 -> h1 (NHWC, pre-bn)
    conv1_kernel<<<dim3(8, 16, BATCH * 4), 256>>>(x, conv1_w, conv1_b);
    // [2][3] bn1 stats
    stats_p1<C1><<<2048, 256>>>(d_h1n);
    stats_p2<C1><<<C1, 256>>>(bn1_g, bn1_b, d_stats1);
    // [4] apply bn1+relu+tf32 in place (4194304 float4 / 256)
    apply1_kernel<<<16384, 256>>>();
    // [5] conv2 mma.sync tf32 -> g_feat NHWC   (ncu -s 5 lands here)
    gemm_conv<4, 2, 0><<<dim3(2, 256, BATCH), 256, smem_c2>>>(
        d_h1n, d_w2p, conv2_b, d_feat);
    // [6][7] bn2 stats
    stats_p1<C2><<<2048, 256>>>(d_feat);
    stats_p2<C2><<<C2, 256>>>(bn2_g, bn2_b, d_stats2);
    // [8] bn2+relu: NCHW features to d_out + tf32 NHWC back to g_feat
    bn2t_kernel<<<dim3(4, 256, BATCH), 256>>>(out);
    // [9] matcher mma.sync tf32 (sigmoid epi) -> AM/ANM slabs
    gemm_conv<2, 4, 1><<<dim3(1, 256, BATCH), 256, smem_mt>>>(
        d_feat, d_mwp, nullptr, out);
    // [10] fused 1x1 head -> remaining 6 output slabs
    head_kernel<<<(BATCH * HW) / 256, 256>>>(out, out, qa1_w, qa1_b, qa2_w, qa2_b,
                                             cls_w, cls_b);
}